// round 16
// baseline (speedup 1.0000x reference)
#include <cuda_runtime.h>
#include <cuda_bf16.h>
#include <cstddef>

// ---------------------------------------------------------------------------
// MS-SSIM, 32x1x512x512 fp32 pairs, 5 levels, 11x11 Gaussian (sigma=1.5).
// SINGLE launch. Vertical strip-chaining: each ssim block processes `chain`
// vertically adjacent 32x32 tiles, keeping a 42-row interleaved hb window
// resident in smem and shifting it by 32 rows per tile (copy 10 rows,
// h-blur 32 new rows). (s,d) basis, packed f32x2.
//   blocks [0,4096): even -> pyramid (2048), odd -> level-0 strips (2048)
//   [4096,4352): level-1 strips (256, chain 8)   waits pyr1_done
//   [4352,4480): level-2 strips (128, chain 4)   waits pyr_done
//   [4480,4544): level-3 strips (64,  chain 2)   waits pyr_done
//   [4544,4576): level-4 strips (32,  chain 1)   waits pyr_done
//   4576: finisher (output + state reset for graph replay)
// ---------------------------------------------------------------------------

#define HALO  5
#define WIN   11

typedef unsigned long long u64;

#define GW0 0.00102839f
#define GW1 0.00759870f
#define GW2 0.03600080f
#define GW3 0.10936070f
#define GW4 0.21300540f
#define GW5 0.26601170f

#define C1F 1.0e-4f
#define C2F 9.0e-4f

#define OFF1 ((size_t)0)
#define OFF2 (OFF1 + (size_t)32 * 256 * 256)
#define OFF3 (OFF2 + (size_t)32 * 128 * 128)
#define OFF4 (OFF3 + (size_t)32 * 64 * 64)

#define N_PYR   2048
#define N_SSIM  2528
#define Z_END   4096
#define L1_END  4352
#define L2_END  4480
#define L3_END  4544
#define L4_END  4576
#define B_FIN   4576

__device__ float  g_buf1[32u * 87040u];
__device__ float  g_buf2[32u * 87040u];
__device__ double g_sums[10];
__device__ int    g_pyr1_done;
__device__ int    g_pyr_done;
__device__ int    g_done;

// ---- f32x2 packed helpers -------------------------------------------------
__device__ __forceinline__ void fma2(u64& d, u64 a, u64 b) {
    asm("fma.rn.f32x2 %0, %1, %2, %0;" : "+l"(d) : "l"(a), "l"(b));
}
__device__ __forceinline__ u64 mul2(u64 a, u64 b) {
    u64 r;
    asm("mul.rn.f32x2 %0, %1, %2;" : "=l"(r) : "l"(a), "l"(b));
    return r;
}
__device__ __forceinline__ u64 pack2(float x, float y) {
    u64 r;
    asm("mov.b64 %0, {%1, %2};" : "=l"(r) : "f"(x), "f"(y));
    return r;
}
__device__ __forceinline__ float lo32(u64 a) {
    float r;
    asm("{ .reg .f32 hi; mov.b64 {%0, hi}, %1; }" : "=f"(r) : "l"(a));
    return r;
}
__device__ __forceinline__ float hi32(u64 a) {
    float r;
    asm("{ .reg .f32 lo; mov.b64 {lo, %0}, %1; }" : "=f"(r) : "l"(a));
    return r;
}

// ---- shared memory --------------------------------------------------------
// stage: 16 input rows (42 cols, u64 packed (s,d)); row = 21 x 16B (odd) ->
//        conflict-free LDS.128 octets.
// hbI:   42-row interleaved window; hbI[r][2c] = SD, hbI[r][2c+1] = PQ.
//        row = 68 u64 = 34 x 16B; v-pass LDS.128 octets bank-distinct.
struct SsimSmem {
    u64   stage[16][42];       // 5.25 KB
    u64   hbI[42][68];         // 22.3 KB
    float wsum[8][2];
};
struct PyrSmem {
    float a1[32][33], a2[32][33];
    float e1[16][17], e2[16][17];
    float c1[8][9],  c2[8][9];
};

__device__ __forceinline__ u64 wsel(int k) {
    const int kk = (k <= 5) ? k : (10 - k);
    switch (kk) {
        case 0:  return pack2(GW0, GW0);
        case 1:  return pack2(GW1, GW1);
        case 2:  return pack2(GW2, GW2);
        case 3:  return pack2(GW3, GW3);
        case 4:  return pack2(GW4, GW4);
        default: return pack2(GW5, GW5);
    }
}

// load n input rows starting at global row g0 into stage[0..n)
__device__ __forceinline__ void load_chunk(
    SsimSmem& S, const float* __restrict__ p1, const float* __restrict__ p2,
    int H, int x0, int g0, int n, int tid)
{
    const int total = n * 42;
    for (int t = tid; t < total; t += 256) {
        const int r  = t / 42;
        const int c  = t - r * 42;
        const int gy = g0 + r;
        const int gx = x0 + c;
        float u = 0.f, v = 0.f;
        if (gy >= 0 && gy < H && gx >= 0 && gx < H) {
            u = p1[(size_t)gy * H + gx];
            v = p2[(size_t)gy * H + gx];
        }
        S.stage[r][c] = pack2(u + v, u - v);
    }
}

// h-blur stage rows [0..n) into hbI rows [hb0..hb0+n). 2-output tasks,
// 16 tasks per row (256 threads cover n=16 exactly).
__device__ __forceinline__ void hpass_chunk(SsimSmem& S, int n, int hb0, int tid)
{
    if (tid < n * 16) {
        const int row = tid >> 4;
        const int pr_ = tid & 15;
        const int c0  = pr_ << 1;
        const ulonglong2* __restrict__ srow2 =
            reinterpret_cast<const ulonglong2*>(&S.stage[row][c0]);

        u64 A0SD = 0ull, A0PQ = 0ull, A1SD = 0ull, A1PQ = 0ull;
#pragma unroll
        for (int ii = 0; ii < 6; ii++) {
            const ulonglong2 pr = srow2[ii];       // LDS.128, conflict-free
#pragma unroll
            for (int h = 0; h < 2; h++) {
                const int i  = 2 * ii + h;
                const u64 sd = h ? pr.y : pr.x;
                const u64 sq = mul2(sd, sd);
                if (i < 11) { fma2(A0SD, wsel(i),     sd); fma2(A0PQ, wsel(i),     sq); }
                if (i >= 1) { fma2(A1SD, wsel(i - 1), sd); fma2(A1PQ, wsel(i - 1), sq); }
            }
        }
        ulonglong2* dst =
            reinterpret_cast<ulonglong2*>(&S.hbI[hb0 + row][c0 << 1]);
        dst[0] = make_ulonglong2(A0SD, A0PQ);      // STS.128
        dst[1] = make_ulonglong2(A1SD, A1PQ);
    }
}

// ---------------------------------------------------------------------------
// Strip body: `chain` vertically adjacent 32x32 output tiles at column bxi.
// ---------------------------------------------------------------------------
__device__ __forceinline__ void ssim_strip(
    int level, int H, int chain, int bxi, int ybase, int b,
    const float* __restrict__ p1base, const float* __restrict__ p2base,
    SsimSmem& S, double* __restrict__ sums, int* __restrict__ done,
    int tx, int ty, int tid)
{
    const float* __restrict__ p1 = p1base + (size_t)b * H * H;
    const float* __restrict__ p2 = p2base + (size_t)b * H * H;
    const int x0 = bxi * 32 - HALO;

    // ---- initial fill: 42 halo rows in chunks of 16/16/10 ----
    int gcur = ybase - HALO;
    load_chunk(S, p1, p2, H, x0, gcur, 16, tid);       __syncthreads();
    hpass_chunk(S, 16, 0, tid);                        __syncthreads();
    load_chunk(S, p1, p2, H, x0, gcur + 16, 16, tid);  __syncthreads();
    hpass_chunk(S, 16, 16, tid);                       __syncthreads();
    load_chunk(S, p1, p2, H, x0, gcur + 32, 10, tid);  __syncthreads();
    hpass_chunk(S, 10, 32, tid);                       __syncthreads();
    gcur += 42;

    float lssim = 0.f, lmcs = 0.f;
    const int r0 = ty << 2;

    for (int t = 0; ; t++) {
        // ---- vertical pass: thread = col tx, rows 4*ty..4*ty+3 ----
        u64 VSD[4] = {0ull, 0ull, 0ull, 0ull};
        u64 VPQ[4] = {0ull, 0ull, 0ull, 0ull};
#pragma unroll
        for (int i = 0; i < 14; i++) {
            const ulonglong2 hv = *reinterpret_cast<const ulonglong2*>(
                &S.hbI[r0 + i][tx << 1]);          // LDS.128 {SD, PQ}
#pragma unroll
            for (int j = 0; j < 4; j++) {
                const int k = i - j;
                if (k >= 0 && k < WIN) {
                    fma2(VSD[j], wsel(k), hv.x);
                    fma2(VPQ[j], wsel(k), hv.y);
                }
            }
        }
#pragma unroll
        for (int j = 0; j < 4; j++) {
            const float ms = lo32(VSD[j]);
            const float md = hi32(VSD[j]);
            const float P  = lo32(VPQ[j]);
            const float Q  = hi32(VPQ[j]);
            const float S2 = ms * ms;
            const float D2 = md * md;
            const float a  = 0.5f * (S2 - D2);     // 2*mu1*mu2
            const float bb = 0.5f * (S2 + D2);     // mu1^2+mu2^2
            const float num2 = 0.5f * (P - Q) - a + C2F;
            const float den2 = 0.5f * (P + Q) - bb + C2F;
            const float mcs  = __fdividef(num2, den2);
            const float ssim = __fdividef(a + C1F, bb + C1F) * mcs;
            lssim += ssim;
            lmcs  += mcs;
        }

        if (t + 1 >= chain) break;

        __syncthreads();   // hb reads of this tile complete

        // shift hbI rows 32..41 -> 0..9 ; concurrently load 16 new rows
        {
            const ulonglong2* __restrict__ src =
                reinterpret_cast<const ulonglong2*>(&S.hbI[32][0]);
            ulonglong2* __restrict__ dst =
                reinterpret_cast<ulonglong2*>(&S.hbI[0][0]);
            for (int t2 = tid; t2 < 340; t2 += 256) dst[t2] = src[t2];
        }
        load_chunk(S, p1, p2, H, x0, gcur, 16, tid);
        __syncthreads();
        hpass_chunk(S, 16, 10, tid);                      __syncthreads();
        load_chunk(S, p1, p2, H, x0, gcur + 16, 16, tid); __syncthreads();
        hpass_chunk(S, 16, 26, tid);                      __syncthreads();
        gcur += 32;
    }

    // ---- strip-level reduction + atomics ----
#pragma unroll
    for (int o = 16; o > 0; o >>= 1) {
        lssim += __shfl_down_sync(0xffffffffu, lssim, o);
        lmcs  += __shfl_down_sync(0xffffffffu, lmcs,  o);
    }
    if (tx == 0) {
        S.wsum[ty][0] = lssim;
        S.wsum[ty][1] = lmcs;
    }
    __syncthreads();
    if (ty == 0 && tx < 8) {
        float a = S.wsum[tx][0];
        float c = S.wsum[tx][1];
#pragma unroll
        for (int o = 4; o > 0; o >>= 1) {
            a += __shfl_down_sync(0xffu, a, o);
            c += __shfl_down_sync(0xffu, c, o);
        }
        if (tx == 0) {
            atomicAdd(&sums[2 * level + 0], (double)a);
            atomicAdd(&sums[2 * level + 1], (double)c);
            __threadfence();
            atomicAdd(done, 1);
        }
    }
}

// ---------------------------------------------------------------------------
__global__ __launch_bounds__(256, 8)
void mega_kernel(const float* __restrict__ img1,
                 const float* __restrict__ img2,
                 float* __restrict__ buf1,
                 float* __restrict__ buf2,
                 double* __restrict__ sums,
                 int* __restrict__ pyr1_done,
                 int* __restrict__ pyr_done,
                 int* __restrict__ done,
                 float* __restrict__ out)
{
    __shared__ __align__(16) unsigned char smraw[sizeof(SsimSmem)];

    const int tx  = threadIdx.x;
    const int ty  = threadIdx.y;
    const int tid = ty * 32 + tx;
    const int gb  = blockIdx.x;

    // ======================= finisher block ================================
    if (gb == B_FIN) {
        if (tid == 0) {
            volatile int* f = done;
            while (*f < N_SSIM) __nanosleep(256);
            __threadfence();

            const float w[5] = {0.0448f, 0.2856f, 0.3001f, 0.2363f, 0.1333f};
            float acc = 0.f;
#pragma unroll
            for (int l = 0; l < 4; l++) {
                const float N = 32.f * (float)(512 >> l) * (float)(512 >> l);
                const float mcs = (float)(sums[2 * l + 1] / (double)N);
                acc += w[l] * __log2f(mcs);
            }
            {
                const float N = 32.f * 32.f * 32.f;
                const float ssim = (float)(sums[2 * 4 + 0] / (double)N);
                acc += w[4] * __log2f(ssim);
            }
            out[0] = exp2f(acc);

#pragma unroll
            for (int i = 0; i < 10; i++) sums[i] = 0.0;
            __threadfence();
            *pyr1_done = 0;
            *pyr_done  = 0;
            *done      = 0;
        }
        return;
    }

    // ============ zone: pyramid (even ids) + level-0 strips (odd) ==========
    if (gb < Z_END) {
        if ((gb & 1) == 0) {
            // ------------------- pyramid block -------------------
            PyrSmem& P = *reinterpret_cast<PyrSmem*>(smraw);
            const int q  = gb >> 1;
            const int bx = q & 7, by = (q >> 3) & 7, b = q >> 6;

            const float* __restrict__ p1 = img1 + (size_t)b * 512 * 512;
            const float* __restrict__ p2 = img2 + (size_t)b * 512 * 512;

#pragma unroll
            for (int it = 0; it < 4; it++) {
                const int o  = tid + 256 * it;
                const int oy = o >> 5, ox = o & 31;
                const size_t r0 = (size_t)(by * 64 + 2 * oy) * 512 + bx * 64 + 2 * ox;
                const float2 u0 = *(const float2*)(p1 + r0);
                const float2 u1 = *(const float2*)(p1 + r0 + 512);
                const float2 v0 = *(const float2*)(p2 + r0);
                const float2 v1 = *(const float2*)(p2 + r0 + 512);
                const float d1 = 0.25f * (u0.x + u0.y + u1.x + u1.y);
                const float d2 = 0.25f * (v0.x + v0.y + v1.x + v1.y);
                P.a1[oy][ox] = d1;
                P.a2[oy][ox] = d2;
                const size_t gi = ((size_t)b * 256 + (by * 32 + oy)) * 256 + (bx * 32 + ox);
                buf1[OFF1 + gi] = d1;
                buf2[OFF1 + gi] = d2;
            }
            __threadfence();
            __syncthreads();
            if (tid == 0) atomicAdd(pyr1_done, 1);

            {
                const int oy = tid >> 4, ox = tid & 15;
                const float d1 = 0.25f * (P.a1[2*oy][2*ox] + P.a1[2*oy][2*ox+1] +
                                          P.a1[2*oy+1][2*ox] + P.a1[2*oy+1][2*ox+1]);
                const float d2 = 0.25f * (P.a2[2*oy][2*ox] + P.a2[2*oy][2*ox+1] +
                                          P.a2[2*oy+1][2*ox] + P.a2[2*oy+1][2*ox+1]);
                P.e1[oy][ox] = d1;
                P.e2[oy][ox] = d2;
                const size_t gi = ((size_t)b * 128 + (by * 16 + oy)) * 128 + (bx * 16 + ox);
                buf1[OFF2 + gi] = d1;
                buf2[OFF2 + gi] = d2;
            }
            __syncthreads();

            if (tid < 64) {
                const int oy = tid >> 3, ox = tid & 7;
                const float d1 = 0.25f * (P.e1[2*oy][2*ox] + P.e1[2*oy][2*ox+1] +
                                          P.e1[2*oy+1][2*ox] + P.e1[2*oy+1][2*ox+1]);
                const float d2 = 0.25f * (P.e2[2*oy][2*ox] + P.e2[2*oy][2*ox+1] +
                                          P.e2[2*oy+1][2*ox] + P.e2[2*oy+1][2*ox+1]);
                P.c1[oy][ox] = d1;
                P.c2[oy][ox] = d2;
                const size_t gi = ((size_t)b * 64 + (by * 8 + oy)) * 64 + (bx * 8 + ox);
                buf1[OFF3 + gi] = d1;
                buf2[OFF3 + gi] = d2;
            }
            __syncthreads();

            if (tid < 16) {
                const int oy = tid >> 2, ox = tid & 3;
                const float d1 = 0.25f * (P.c1[2*oy][2*ox] + P.c1[2*oy][2*ox+1] +
                                          P.c1[2*oy+1][2*ox] + P.c1[2*oy+1][2*ox+1]);
                const float d2 = 0.25f * (P.c2[2*oy][2*ox] + P.c2[2*oy][2*ox+1] +
                                          P.c2[2*oy+1][2*ox] + P.c2[2*oy+1][2*ox+1]);
                const size_t gi = ((size_t)b * 32 + (by * 4 + oy)) * 32 + (bx * 4 + ox);
                buf1[OFF4 + gi] = d1;
                buf2[OFF4 + gi] = d2;
            }
            __threadfence();
            __syncthreads();
            if (tid == 0) atomicAdd(pyr_done, 1);
            return;
        }

        // ------------------- level-0 strip -------------------
        SsimSmem& S = *reinterpret_cast<SsimSmem*>(smraw);
        const int idx = gb >> 1;            // 0..2047
        const int b   = idx >> 6;
        const int rem = idx & 63;
        const int syi = rem >> 4;           // strip 0..3
        const int bxi = rem & 15;
        ssim_strip(0, 512, 4, bxi, syi * 128, b, img1, img2,
                   S, sums, done, tx, ty, tid);
        return;
    }

    // ======================= levels 1..4 strips ============================
    SsimSmem& S = *reinterpret_cast<SsimSmem*>(smraw);

    int level, H, chain, b, bxi;
    const float *p1base, *p2base;
    if (gb < L1_END) {
        level = 1; H = 256; chain = 8;
        const int idx = gb - Z_END;   b = idx >> 3; bxi = idx & 7;
        p1base = buf1 + OFF1; p2base = buf2 + OFF1;
    } else if (gb < L2_END) {
        level = 2; H = 128; chain = 4;
        const int idx = gb - L1_END;  b = idx >> 2; bxi = idx & 3;
        p1base = buf1 + OFF2; p2base = buf2 + OFF2;
    } else if (gb < L3_END) {
        level = 3; H = 64;  chain = 2;
        const int idx = gb - L2_END;  b = idx >> 1; bxi = idx & 1;
        p1base = buf1 + OFF3; p2base = buf2 + OFF3;
    } else {
        level = 4; H = 32;  chain = 1;
        b = gb - L3_END;              bxi = 0;
        p1base = buf1 + OFF4; p2base = buf2 + OFF4;
    }

    if (level == 1) {
        if (tid == 0) {
            volatile int* f = pyr1_done;
            while (*f < N_PYR) __nanosleep(128);
            __threadfence();
        }
        __syncthreads();
    } else {
        if (tid == 0) {
            volatile int* f = pyr_done;
            while (*f < N_PYR) __nanosleep(128);
            __threadfence();
        }
        __syncthreads();
    }

    ssim_strip(level, H, chain, bxi, 0, b, p1base, p2base,
               S, sums, done, tx, ty, tid);
}

extern "C" void kernel_launch(void* const* d_in, const int* in_sizes, int n_in,
                              void* d_out, int out_size)
{
    const float* img1 = (const float*)d_in[0];
    const float* img2 = (const float*)d_in[1];
    float* out = (float*)d_out;

    double* sums = nullptr;
    float*  buf1 = nullptr;
    float*  buf2 = nullptr;
    int *f1 = nullptr, *f2 = nullptr, *f3 = nullptr;
    cudaGetSymbolAddress((void**)&sums, g_sums);
    cudaGetSymbolAddress((void**)&buf1, g_buf1);
    cudaGetSymbolAddress((void**)&buf2, g_buf2);
    cudaGetSymbolAddress((void**)&f1, g_pyr1_done);
    cudaGetSymbolAddress((void**)&f2, g_pyr_done);
    cudaGetSymbolAddress((void**)&f3, g_done);

    mega_kernel<<<B_FIN + 1, dim3(32, 8)>>>(img1, img2, buf1, buf2,
                                            sums, f1, f2, f3, out);
}